// round 15
// baseline (speedup 1.0000x reference)
#include <cuda_runtime.h>
#include <cstdint>
#include <math.h>

#define Hdim 2048
#define Bdim 16
#define Tdim 1024
#define NIN 8
#define NOUT 8
#define TUNED 10
#define NCTA 128
#define RPC 16
#define NTH 256
#define KC 512
#define NCH 4
#define DTC 0.001f
#define BETAC 1.5f
#define PAD 32

typedef unsigned long long u64;

__device__ float g_Wm[Hdim * Hdim];
__device__ float g_v[2][Bdim * Hdim];
__device__ float g_zt[Tdim * NCTA * 128];
__device__ float g_zp0[NCTA * 128];
__device__ unsigned g_wcnt[NCH * PAD];
__device__ unsigned g_zcnt[PAD];
__device__ int g_zflag;

__device__ __forceinline__ void cp16(float* d, const float* s) {
    unsigned ds = (unsigned)__cvta_generic_to_shared(d);
    asm volatile("cp.async.cg.shared.global [%0],[%1],16;" ::"r"(ds), "l"(s));
}
__device__ __forceinline__ unsigned ldacq(const unsigned* p) {
    unsigned v;
    asm volatile("ld.acquire.gpu.global.u32 %0,[%1];" : "=r"(v) : "l"(p));
    return v;
}
__device__ __forceinline__ void red_release(unsigned* p) {
    asm volatile("red.release.gpu.global.add.u32 [%0],1;" ::"l"(p) : "memory");
}
__device__ __forceinline__ void stcs(float* p, float v) {
    asm volatile("st.global.cs.f32 [%0],%1;" ::"l"(p), "f"(v));
}
__device__ __forceinline__ u64 fma2(u64 a, u64 b, u64 c) {
    u64 d;
    asm("fma.rn.f32x2 %0,%1,%2,%3;" : "=l"(d) : "l"(a), "l"(b), "l"(c));
    return d;
}
__device__ __forceinline__ float unpack_sum(u64 v) {
    float lo, hi;
    asm("mov.b64 {%0,%1},%2;" : "=f"(lo), "=f"(hi) : "l"(v));
    return lo + hi;
}
__device__ __forceinline__ float my_tanh(float x) {
    float e;
    asm("ex2.approx.f32 %0, %1;" : "=f"(e) : "f"(fabsf(x) * 2.8853900817779268f));
    float y = e + 1.0f;
    float r0;
    asm("rcp.approx.f32 %0, %1;" : "=f"(r0) : "f"(y));
    r0 = r0 * fmaf(-y, r0, 2.0f);
    float res = fmaf(-2.0f, r0, 1.0f);
    return copysignf(res, x);
}
__device__ __forceinline__ float merge32(float* a, int l) {
#pragma unroll
    for (int k = 0; k < 5; k++) {
        const int m = 1 << k;
        const bool s = (l >> k) & 1;
#pragma unroll
        for (int i = 0; i < (32 >> (k + 1)); i++) {
            float A = a[2 * i], B = a[2 * i + 1];
            float keep = s ? B : A;
            float send = s ? A : B;
            a[i] = keep + __shfl_xor_sync(0xffffffffu, send, m);
        }
    }
    return a[0];
}

__global__ void reset_counters() {
    int i = threadIdx.x;
    if (i < NCH * PAD) g_wcnt[i] = 0u;
    if (i < PAD) g_zcnt[i] = 0u;
    if (i == 0) g_zflag = 0;
}
__global__ void scan_wzh(const float* __restrict__ wzh) {
    int i = blockIdx.x * 256 + threadIdx.x;
    if (i < Hdim * NOUT && wzh[i] != 0.0f) g_zflag = 1;
}
__global__ void build_wm(const float* __restrict__ wt, const float* __restrict__ wf,
                         const float* __restrict__ mk) {
    int idx = blockIdx.x * 256 + threadIdx.x;
    if (idx < Hdim * Hdim) {
        int j = idx >> 11, k = idx & (Hdim - 1);
        float w = (k < TUNED) ? wt[j * TUNED + k] : wf[j * (Hdim - TUNED) + (k - TUNED)];
        g_Wm[idx] = mk[idx] * w;
    }
}
__global__ void zred(float* __restrict__ out_z) {
    int idx = blockIdx.x * 256 + threadIdx.x;
    int t = idx >> 7, bo = idx & 127;
    const float* p = g_zt + (size_t)t * (NCTA * 128) + bo;
    float s = 0.f;
#pragma unroll 8
    for (int c = 0; c < NCTA; c++) s += __ldcg(p + c * 128);
    out_z[((size_t)(bo >> 3) * Tdim + t) * NOUT + (bo & 7)] = s;
}

__device__ __forceinline__ void prefetch(float* sV, const float* vsrc, int slot, int c, int tid) {
    float* dst = sV + slot * (Bdim * KC);
    const float* src = vsrc + c * KC;
#pragma unroll
    for (int u = 0; u < 8; u++) {
        int seg = u * NTH + tid;
        int b = seg >> 7;
        int f = (seg & 127) << 2;
        cp16(dst + b * KC + f, src + (size_t)b * Hdim + f);
    }
    asm volatile("cp.async.commit_group;" ::: "memory");
}

__device__ __forceinline__ void chunk_fma(const float* sWm, const float* sV, u64* acc,
                                          int jbase, int bbase, int kgo, int l,
                                          int c, int slot) {
    const float* Wp = sWm + jbase * Hdim + c * KC + kgo + (l << 2);
    const float* Vp = sV + slot * (Bdim * KC) + bbase * KC + kgo + (l << 2);
#pragma unroll
    for (int it = 0; it < 2; it++) {
        ulonglong2 wv[8], vv[8];
#pragma unroll
        for (int rr = 0; rr < 8; rr++)
            wv[rr] = *(const ulonglong2*)(Wp + rr * Hdim + it * 128);
#pragma unroll
        for (int q = 0; q < 8; q++)
            vv[q] = *(const ulonglong2*)(Vp + q * KC + it * 128);
#pragma unroll
        for (int rr = 0; rr < 8; rr++)
#pragma unroll
            for (int q = 0; q < 8; q++) {
                u64 A = acc[rr * 8 + q];
                A = fma2(wv[rr].x, vv[q].x, A);
                A = fma2(wv[rr].y, vv[q].y, A);
                acc[rr * 8 + q] = A;
            }
    }
}

// single acquire-loop poll (one L2 round trip when not ready)
__device__ __forceinline__ void warp_poll_cond(bool pre, const unsigned* p, unsigned tgt, int lane) {
    if (lane == 0 && !pre) {
        while (ldacq(p) < tgt) {}
    }
    __syncwarp();
}

__global__ __launch_bounds__(NTH, 1) void rnn_persist(
    const float* __restrict__ x, const float* __restrict__ h0,
    const float* __restrict__ Wih, const float* __restrict__ Whz,
    const float* __restrict__ Wzh, const float* __restrict__ tau,
    float* __restrict__ out) {

    extern __shared__ float sm[];
    float* sWm = sm;              // 32768
    float* sV  = sm + 32768;      // 16384
    float* sHT = sm + 49152;      // 256  [j*16+b]
    float* sZ  = sm + 49408;      // 128  (zf fallback)
    float* sX  = sm + 49536;      // 128  [b*8+i]
    float* sWi = sm + 49664;      // 128
    float* sWz = sm + 49792;      // 128
    float* sWo = sm + 49920;      // 128  [o*16+j]
    float* sTa = sm + 50048;      // 16
    float* sP  = sm + 50064;      // 512

    const int tid = threadIdx.x;
    const int cta = blockIdx.x;
    const int l = tid & 31, w = tid >> 5;
    const int rg = w & 1, bg = (w >> 1) & 1, kg = w >> 2;
    const int jbase = rg * 8, bbase = bg * 8, kgo = kg * 256;
    const int jl = tid >> 4, b = tid & 15;
    const int jrow = cta * RPC;
    const int myg = cta >> 5;
    const int zf = g_zflag;

    float* out_h = out + (size_t)Bdim * Tdim * NOUT;
    float* out_r = out_h + (size_t)Bdim * Tdim * Hdim;

    const int c0 = myg, c1 = (myg + 1) & 3, c2 = (myg + 2) & 3, c3 = (myg + 3) & 3;
    const unsigned* pc0 = &g_wcnt[c0 * PAD];
    const unsigned* pc1 = &g_wcnt[c1 * PAD];
    const unsigned* pc2 = &g_wcnt[c2 * PAD];
    const unsigned* pc3 = &g_wcnt[c3 * PAD];

    // ---- one-time loads ----
    {
        const float4* src = (const float4*)(g_Wm + (size_t)jrow * Hdim);
        float4* dst = (float4*)sWm;
#pragma unroll 8
        for (int i = tid; i < RPC * Hdim / 4; i += NTH) dst[i] = src[i];
    }
    if (tid < 128) {
        int jj = tid >> 3, ii = tid & 7;
        sWi[tid] = Wih[(jrow + jj) * NIN + ii];
        sWz[tid] = Wzh[(jrow + jj) * NOUT + ii];
        int oo = tid >> 4, j2 = tid & 15;
        sWo[tid] = Whz[oo * Hdim + jrow + j2];
    }
    if (tid < RPC) sTa[tid] = tau[jrow + tid];
    __syncthreads();

    // ---- init state (one cell per thread) ----
    const float itau = 1.0f / sTa[jl];
    float h = h0[(size_t)b * Hdim + jrow + jl];
    float r = 1.0f;
    float hT = my_tanh(h);
    __stcg(&g_v[0][b * Hdim + jrow + jl], hT);    // r0=1 -> v0 = tanh(h0)
    sHT[jl * 16 + b] = hT;
    __syncthreads();
    if (zf && tid < 128) {
        int bb2 = tid >> 3, oo = tid & 7;
        float s = 0.f;
#pragma unroll
        for (int j2 = 0; j2 < RPC; j2++) s = fmaf(sHT[j2 * 16 + bb2], sWo[oo * 16 + j2], s);
        __stcg(&g_zp0[cta * 128 + tid], s);
    }
    __syncthreads();
    if (tid == 0) {
        red_release(&g_wcnt[myg * PAD]);
        if (zf) red_release(&g_zcnt[0]);
    }

    // ---- preloop: wait own group for step 0, snapshot, prefetch c0 ----
    unsigned tgt = 32u;
    bool f1 = false, f2 = false, f3 = false;
    if (l == 0) {
        while (ldacq(pc0) < tgt) {}
        f1 = (ldacq(pc1) >= tgt);
        f2 = (ldacq(pc2) >= tgt);
        f3 = (ldacq(pc3) >= tgt);
    }
    __syncwarp();
    prefetch(sV, g_v[0], 0, c0, tid);

    // ---- time loop ----
    for (int t = 0; t < Tdim; t++) {
        const int nb = (t & 1) ^ 1;
        const float* vsrc = g_v[t & 1];

        if (tid < 128)
            sX[tid] = x[((size_t)(tid >> 3) * Tdim + t) * NIN + (tid & 7)];
        if (zf) {
            if (tid == 0) {
                unsigned zt_ = 128u * (unsigned)(t + 1);
                while (ldacq(&g_zcnt[0]) < zt_) {}
            }
            __syncthreads();
            if (tid < 128) {
                const float* zp = (t == 0) ? (g_zp0 + tid)
                                           : (g_zt + (size_t)(t - 1) * (NCTA * 128) + tid);
                float s = 0.f;
#pragma unroll 8
                for (int q = 0; q < NCTA; q++) s += __ldcg(zp + q * 128);
                sZ[tid] = s;
            }
        }

        u64 acc[64];
#pragma unroll
        for (int i = 0; i < 64; i++) acc[i] = 0ull;

        // iter 0: c0 (slot0) ; start c1 -> slot1
        asm volatile("cp.async.wait_group 0;" ::: "memory");
        __syncthreads();
        warp_poll_cond(f1, pc1, tgt, l);
        prefetch(sV, vsrc, 1, c1, tid);
        chunk_fma(sWm, sV, acc, jbase, bbase, kgo, l, c0, 0);
        // iter 1: c1 (slot1) ; start c2 -> slot0
        asm volatile("cp.async.wait_group 0;" ::: "memory");
        __syncthreads();
        warp_poll_cond(f2, pc2, tgt, l);
        prefetch(sV, vsrc, 0, c2, tid);
        chunk_fma(sWm, sV, acc, jbase, bbase, kgo, l, c1, 1);
        // iter 2: c2 (slot0) ; start c3 -> slot1
        asm volatile("cp.async.wait_group 0;" ::: "memory");
        __syncthreads();
        warp_poll_cond(f3, pc3, tgt, l);
        prefetch(sV, vsrc, 1, c3, tid);
        chunk_fma(sWm, sV, acc, jbase, bbase, kgo, l, c2, 0);
        // iter 3: c3 (slot1)
        asm volatile("cp.async.wait_group 0;" ::: "memory");
        __syncthreads();
        chunk_fma(sWm, sV, acc, jbase, bbase, kgo, l, c3, 1);

        // ---- reduce: per-warp shfl merge, then cross-kg combine via smem ----
        {
            float a[32];
#pragma unroll
            for (int i = 0; i < 32; i++) a[i] = unpack_sum(acc[i]);
            float recA = merge32(a, l);
#pragma unroll
            for (int i = 0; i < 32; i++) a[i] = unpack_sum(acc[32 + i]);
            float recB = merge32(a, l);
            int cellA = (jbase + (l >> 3)) * 16 + bbase + (l & 7);
            sP[kg * 256 + cellA] = recA;
            sP[kg * 256 + cellA + 64] = recB;
        }
        __syncthreads();

        // ---- state update (owner thread per cell) ----
        {
            float rec = sP[tid] + sP[256 + tid];
            float inx = 0.f, zt = 0.f;
#pragma unroll
            for (int i = 0; i < NIN; i++) inx = fmaf(sX[b * 8 + i], sWi[jl * 8 + i], inx);
            if (zf) {
#pragma unroll
                for (int o = 0; o < NOUT; o++) zt = fmaf(sZ[b * 8 + o], sWz[jl * 8 + o], zt);
            }
            float rs = fmaf(-BETAC * r, hT, (1.0f - r) * itau);
            float rN = fmaf(rs, DTC, r);
            float s = rec + inx + zt - h;
            float hN = fmaf(s, 0.1f, h);          // (s/TAU)*DT = s*0.1
            float hTN = my_tanh(hN);

            size_t oidx = ((size_t)b * Tdim + t) * Hdim + jrow + jl;
            stcs(&out_h[oidx], hN);
            stcs(&out_r[oidx], rN);
            __stcg(&g_v[nb][b * Hdim + jrow + jl], rN * hTN);
            sHT[jl * 16 + b] = hTN;
            h = hN; r = rN; hT = hTN;
        }
        __syncthreads();

        // release v[nb] (critical path)
        if (tid == 0) red_release(&g_wcnt[myg * PAD]);
        // z partial (output path; feedback source only when zf)
        if (tid < 128) {
            int bb2 = tid >> 3, oo = tid & 7;
            float s = 0.f;
#pragma unroll
            for (int j2 = 0; j2 < RPC; j2++) s = fmaf(sHT[j2 * 16 + bb2], sWo[oo * 16 + j2], s);
            stcs(&g_zt[(size_t)t * (NCTA * 128) + cta * 128 + tid], s);
        }
        if (zf) {
            __syncthreads();
            if (tid == 0) red_release(&g_zcnt[0]);
        }

        // ---- hoisted head of step t+1: wait own group, snapshot, prefetch c0 ----
        if (t + 1 < Tdim) {
            tgt += 32u;
            if (l == 0) {
                while (ldacq(pc0) < tgt) {}
                f1 = (ldacq(pc1) >= tgt);
                f2 = (ldacq(pc2) >= tgt);
                f3 = (ldacq(pc3) >= tgt);
            }
            __syncwarp();
            prefetch(sV, g_v[nb], 0, c0, tid);
        }
    }
}

extern "C" void kernel_launch(void* const* d_in, const int* in_sizes, int n_in,
                              void* d_out, int out_size) {
    const float* x   = (const float*)d_in[0];
    const float* h0  = (const float*)d_in[1];
    const float* Wih = (const float*)d_in[2];
    const float* Wt  = (const float*)d_in[3];
    const float* Wf  = (const float*)d_in[4];
    const float* mk  = (const float*)d_in[5];
    const float* Whz = (const float*)d_in[6];
    const float* Wzh = (const float*)d_in[7];
    const float* tau = (const float*)d_in[8];
    float* out = (float*)d_out;

    reset_counters<<<1, 256>>>();
    scan_wzh<<<(Hdim * NOUT + 255) / 256, 256>>>(Wzh);
    build_wm<<<(Hdim * Hdim + 255) / 256, 256>>>(Wt, Wf, mk);

    cudaFuncSetAttribute(rnn_persist, cudaFuncAttributeMaxDynamicSharedMemorySize, 50576 * 4);
    rnn_persist<<<NCTA, NTH, 50576 * 4>>>(x, h0, Wih, Whz, Wzh, tau, out);

    zred<<<(Tdim * 128) / 256, 256>>>(out);
}

// round 16
// speedup vs baseline: 1.5472x; 1.5472x over previous
#include <cuda_runtime.h>
#include <cstdint>
#include <math.h>

#define Hdim 2048
#define Bdim 16
#define Tdim 1024
#define NIN 8
#define NOUT 8
#define TUNED 10
#define NCTA 128
#define RPC 16
#define NTH 256
#define KC 512
#define NCH 4
#define DTC 0.001f
#define BETAC 1.5f
#define PAD 32

typedef unsigned long long u64;

__device__ float g_Wm[Hdim * Hdim];
__device__ float g_v[2][Bdim * Hdim];
__device__ float g_zt[Tdim * NCTA * 128];
__device__ float g_zp0[NCTA * 128];
__device__ unsigned g_wcnt[NCH * PAD];
__device__ unsigned g_zcnt[PAD];
__device__ int g_zflag;

__device__ __forceinline__ void cp16(float* d, const float* s) {
    unsigned ds = (unsigned)__cvta_generic_to_shared(d);
    asm volatile("cp.async.cg.shared.global [%0],[%1],16;" ::"r"(ds), "l"(s));
}
__device__ __forceinline__ unsigned ldrelax(const unsigned* p) {
    unsigned v;
    asm volatile("ld.relaxed.gpu.global.u32 %0,[%1];" : "=r"(v) : "l"(p));
    return v;
}
__device__ __forceinline__ unsigned ldacq(const unsigned* p) {
    unsigned v;
    asm volatile("ld.acquire.gpu.global.u32 %0,[%1];" : "=r"(v) : "l"(p));
    return v;
}
__device__ __forceinline__ void red_release(unsigned* p) {
    asm volatile("red.release.gpu.global.add.u32 [%0],1;" ::"l"(p) : "memory");
}
__device__ __forceinline__ void stcs(float* p, float v) {
    asm volatile("st.global.cs.f32 [%0],%1;" ::"l"(p), "f"(v));
}
__device__ __forceinline__ u64 fma2(u64 a, u64 b, u64 c) {
    u64 d;
    asm("fma.rn.f32x2 %0,%1,%2,%3;" : "=l"(d) : "l"(a), "l"(b), "l"(c));
    return d;
}
__device__ __forceinline__ float unpack_sum(u64 v) {
    float lo, hi;
    asm("mov.b64 {%0,%1},%2;" : "=f"(lo), "=f"(hi) : "l"(v));
    return lo + hi;
}
__device__ __forceinline__ float my_tanh(float x) {
    float e;
    asm("ex2.approx.f32 %0, %1;" : "=f"(e) : "f"(fabsf(x) * 2.8853900817779268f));
    float y = e + 1.0f;
    float r0;
    asm("rcp.approx.f32 %0, %1;" : "=f"(r0) : "f"(y));
    r0 = r0 * fmaf(-y, r0, 2.0f);
    float res = fmaf(-2.0f, r0, 1.0f);
    return copysignf(res, x);
}
__device__ __forceinline__ float merge32(float* a, int l) {
#pragma unroll
    for (int k = 0; k < 5; k++) {
        const int m = 1 << k;
        const bool s = (l >> k) & 1;
#pragma unroll
        for (int i = 0; i < (32 >> (k + 1)); i++) {
            float A = a[2 * i], B = a[2 * i + 1];
            float keep = s ? B : A;
            float send = s ? A : B;
            a[i] = keep + __shfl_xor_sync(0xffffffffu, send, m);
        }
    }
    return a[0];
}

__global__ void reset_counters() {
    int i = threadIdx.x;
    if (i < NCH * PAD) g_wcnt[i] = 0u;
    if (i < PAD) g_zcnt[i] = 0u;
    if (i == 0) g_zflag = 0;
}
__global__ void scan_wzh(const float* __restrict__ wzh) {
    int i = blockIdx.x * 256 + threadIdx.x;
    if (i < Hdim * NOUT && wzh[i] != 0.0f) g_zflag = 1;
}
__global__ void build_wm(const float* __restrict__ wt, const float* __restrict__ wf,
                         const float* __restrict__ mk) {
    int idx = blockIdx.x * 256 + threadIdx.x;
    if (idx < Hdim * Hdim) {
        int j = idx >> 11, k = idx & (Hdim - 1);
        float w = (k < TUNED) ? wt[j * TUNED + k] : wf[j * (Hdim - TUNED) + (k - TUNED)];
        g_Wm[idx] = mk[idx] * w;
    }
}
__global__ void zred(float* __restrict__ out_z) {
    int idx = blockIdx.x * 256 + threadIdx.x;
    int t = idx >> 7, bo = idx & 127;
    const float* p = g_zt + (size_t)t * (NCTA * 128) + bo;
    float s = 0.f;
#pragma unroll 8
    for (int c = 0; c < NCTA; c++) s += __ldcg(p + c * 128);
    out_z[((size_t)(bo >> 3) * Tdim + t) * NOUT + (bo & 7)] = s;
}

__device__ __forceinline__ void prefetch(float* sV, const float* vsrc, int slot, int c, int tid) {
    float* dst = sV + slot * (Bdim * KC);
    const float* src = vsrc + c * KC;
#pragma unroll
    for (int u = 0; u < 8; u++) {
        int seg = u * NTH + tid;
        int b = seg >> 7;
        int f = (seg & 127) << 2;
        cp16(dst + b * KC + f, src + (size_t)b * Hdim + f);
    }
    asm volatile("cp.async.commit_group;" ::: "memory");
}

__device__ __forceinline__ void chunk_fma(const float* sWm, const float* sV, u64* acc,
                                          int jbase, int bbase, int kgo, int l,
                                          int c, int slot) {
    const float* Wp = sWm + jbase * Hdim + c * KC + kgo + (l << 2);
    const float* Vp = sV + slot * (Bdim * KC) + bbase * KC + kgo + (l << 2);
#pragma unroll
    for (int it = 0; it < 2; it++) {
        ulonglong2 wv[8], vv[8];
#pragma unroll
        for (int rr = 0; rr < 8; rr++)
            wv[rr] = *(const ulonglong2*)(Wp + rr * Hdim + it * 128);
#pragma unroll
        for (int q = 0; q < 8; q++)
            vv[q] = *(const ulonglong2*)(Vp + q * KC + it * 128);
#pragma unroll
        for (int rr = 0; rr < 8; rr++)
#pragma unroll
            for (int q = 0; q < 8; q++) {
                u64 A = acc[rr * 8 + q];
                A = fma2(wv[rr].x, vv[q].x, A);
                A = fma2(wv[rr].y, vv[q].y, A);
                acc[rr * 8 + q] = A;
            }
    }
}

// two-phase poll: relaxed spin (cheap at LTS), single acquire confirm
__device__ __forceinline__ void warp_poll_cond(bool pre, const unsigned* p, unsigned tgt, int lane) {
    if (lane == 0 && !pre) {
        while (ldrelax(p) < tgt) {}
        while (ldacq(p) < tgt) {}
    }
    __syncwarp();
}

__global__ __launch_bounds__(NTH, 1) void rnn_persist(
    const float* __restrict__ x, const float* __restrict__ h0,
    const float* __restrict__ Wih, const float* __restrict__ Whz,
    const float* __restrict__ Wzh, const float* __restrict__ tau,
    float* __restrict__ out) {

    extern __shared__ float sm[];
    float* sWm = sm;              // 32768
    float* sV  = sm + 32768;      // 16384
    float* sHT = sm + 49152;      // 256  [j*16+b]
    float* sZ  = sm + 49408;      // 128  (zf fallback)
    float* sX  = sm + 49536;      // 128  [b*8+i]
    float* sWi = sm + 49664;      // 128
    float* sWz = sm + 49792;      // 128
    float* sWo = sm + 49920;      // 128  [o*16+j]
    float* sTa = sm + 50048;      // 16
    float* sP  = sm + 50064;      // 512
    float* sVO = sm + 50576;      // 272  staged v   [jl*17+b]
    float* sHO = sm + 50848;      // 272  staged h
    float* sRO = sm + 51120;      // 272  staged r

    const int tid = threadIdx.x;
    const int cta = blockIdx.x;
    const int l = tid & 31, w = tid >> 5;
    const int rg = w & 1, bg = (w >> 1) & 1, kg = w >> 2;
    const int jbase = rg * 8, bbase = bg * 8, kgo = kg * 256;
    const int jl = tid >> 4, b = tid & 15;
    const int jlT = tid & 15, bT = tid >> 4;    // transposed (coalesced-store) role
    const int jrow = cta * RPC;
    const int myg = cta >> 5;
    const int zf = g_zflag;

    float* out_h = out + (size_t)Bdim * Tdim * NOUT;
    float* out_r = out_h + (size_t)Bdim * Tdim * Hdim;

    const int c0 = myg, c1 = (myg + 1) & 3, c2 = (myg + 2) & 3, c3 = (myg + 3) & 3;
    const unsigned* pc0 = &g_wcnt[c0 * PAD];
    const unsigned* pc1 = &g_wcnt[c1 * PAD];
    const unsigned* pc2 = &g_wcnt[c2 * PAD];
    const unsigned* pc3 = &g_wcnt[c3 * PAD];

    // ---- one-time loads ----
    {
        const float4* src = (const float4*)(g_Wm + (size_t)jrow * Hdim);
        float4* dst = (float4*)sWm;
#pragma unroll 8
        for (int i = tid; i < RPC * Hdim / 4; i += NTH) dst[i] = src[i];
    }
    if (tid < 128) {
        int jj = tid >> 3, ii = tid & 7;
        sWi[tid] = Wih[(jrow + jj) * NIN + ii];
        sWz[tid] = Wzh[(jrow + jj) * NOUT + ii];
        int oo = tid >> 4, j2 = tid & 15;
        sWo[tid] = Whz[oo * Hdim + jrow + j2];
    }
    if (tid < RPC) sTa[tid] = tau[jrow + tid];
    __syncthreads();

    // ---- init state (one cell per thread) ----
    const float itau = 1.0f / sTa[jl];
    float h = h0[(size_t)b * Hdim + jrow + jl];
    float r = 1.0f;
    float hT = my_tanh(h);
    sVO[jl * 17 + b] = hT;                        // r0=1 -> v0 = tanh(h0)
    sHT[jl * 16 + b] = hT;
    __syncthreads();
    __stcg(&g_v[0][bT * Hdim + jrow + jlT], sVO[jlT * 17 + bT]);  // coalesced
    if (zf && tid < 128) {
        int bb2 = tid >> 3, oo = tid & 7;
        float s = 0.f;
#pragma unroll
        for (int j2 = 0; j2 < RPC; j2++) s = fmaf(sHT[j2 * 16 + bb2], sWo[oo * 16 + j2], s);
        __stcg(&g_zp0[cta * 128 + tid], s);
    }
    __syncthreads();
    if (tid == 0) {
        red_release(&g_wcnt[myg * PAD]);
        if (zf) red_release(&g_zcnt[0]);
    }

    // ---- preloop: wait own group for step 0, snapshot, prefetch c0 ----
    unsigned tgt = 32u;
    bool f1 = false, f2 = false, f3 = false;
    if (l == 0) {
        while (ldrelax(pc0) < tgt) {}
        while (ldacq(pc0) < tgt) {}
        f1 = (ldacq(pc1) >= tgt);
        f2 = (ldacq(pc2) >= tgt);
        f3 = (ldacq(pc3) >= tgt);
    }
    __syncwarp();
    prefetch(sV, g_v[0], 0, c0, tid);

    // ---- time loop ----
    for (int t = 0; t < Tdim; t++) {
        const int nb = (t & 1) ^ 1;
        const float* vsrc = g_v[t & 1];

        if (tid < 128)
            sX[tid] = x[((size_t)(tid >> 3) * Tdim + t) * NIN + (tid & 7)];
        if (zf) {
            if (tid == 0) {
                unsigned zt_ = 128u * (unsigned)(t + 1);
                while (ldrelax(&g_zcnt[0]) < zt_) {}
                while (ldacq(&g_zcnt[0]) < zt_) {}
            }
            __syncthreads();
            if (tid < 128) {
                const float* zp = (t == 0) ? (g_zp0 + tid)
                                           : (g_zt + (size_t)(t - 1) * (NCTA * 128) + tid);
                float s = 0.f;
#pragma unroll 8
                for (int q = 0; q < NCTA; q++) s += __ldcg(zp + q * 128);
                sZ[tid] = s;
            }
        }

        u64 acc[64];
#pragma unroll
        for (int i = 0; i < 64; i++) acc[i] = 0ull;

        // iter 0: c0 (slot0) ; start c1 -> slot1
        asm volatile("cp.async.wait_group 0;" ::: "memory");
        __syncthreads();
        warp_poll_cond(f1, pc1, tgt, l);
        prefetch(sV, vsrc, 1, c1, tid);
        chunk_fma(sWm, sV, acc, jbase, bbase, kgo, l, c0, 0);
        // iter 1: c1 (slot1) ; start c2 -> slot0
        asm volatile("cp.async.wait_group 0;" ::: "memory");
        __syncthreads();
        warp_poll_cond(f2, pc2, tgt, l);
        prefetch(sV, vsrc, 0, c2, tid);
        chunk_fma(sWm, sV, acc, jbase, bbase, kgo, l, c1, 1);
        // iter 2: c2 (slot0) ; start c3 -> slot1
        asm volatile("cp.async.wait_group 0;" ::: "memory");
        __syncthreads();
        warp_poll_cond(f3, pc3, tgt, l);
        prefetch(sV, vsrc, 1, c3, tid);
        chunk_fma(sWm, sV, acc, jbase, bbase, kgo, l, c2, 0);
        // iter 3: c3 (slot1)
        asm volatile("cp.async.wait_group 0;" ::: "memory");
        __syncthreads();
        chunk_fma(sWm, sV, acc, jbase, bbase, kgo, l, c3, 1);

        // ---- reduce: per-warp shfl merge, then cross-kg combine via smem ----
        {
            float a[32];
#pragma unroll
            for (int i = 0; i < 32; i++) a[i] = unpack_sum(acc[i]);
            float recA = merge32(a, l);
#pragma unroll
            for (int i = 0; i < 32; i++) a[i] = unpack_sum(acc[32 + i]);
            float recB = merge32(a, l);
            int cellA = (jbase + (l >> 3)) * 16 + bbase + (l & 7);
            sP[kg * 256 + cellA] = recA;
            sP[kg * 256 + cellA + 64] = recB;
        }
        __syncthreads();

        // ---- state update: all results staged to smem (no scattered STG) ----
        {
            float rec = sP[tid] + sP[256 + tid];
            float inx = 0.f, zt = 0.f;
#pragma unroll
            for (int i = 0; i < NIN; i++) inx = fmaf(sX[b * 8 + i], sWi[jl * 8 + i], inx);
            if (zf) {
#pragma unroll
                for (int o = 0; o < NOUT; o++) zt = fmaf(sZ[b * 8 + o], sWz[jl * 8 + o], zt);
            }
            float rs = fmaf(-BETAC * r, hT, (1.0f - r) * itau);
            float rN = fmaf(rs, DTC, r);
            float s = rec + inx + zt - h;
            float hN = fmaf(s, 0.1f, h);          // (s/TAU)*DT = s*0.1
            float hTN = my_tanh(hN);

            int si = jl * 17 + b;
            sVO[si] = rN * hTN;
            sHO[si] = hN;
            sRO[si] = rN;
            sHT[jl * 16 + b] = hTN;
            h = hN; r = rN; hT = hTN;
        }
        __syncthreads();

        // ---- coalesced v publish (critical path), then release ----
        __stcg(&g_v[nb][bT * Hdim + jrow + jlT], sVO[jlT * 17 + bT]);
        __syncthreads();
        if (tid == 0) red_release(&g_wcnt[myg * PAD]);

        // ---- outputs (post-release, coalesced) ----
        {
            size_t oi = ((size_t)bT * Tdim + t) * Hdim + jrow + jlT;
            int si = jlT * 17 + bT;
            stcs(&out_h[oi], sHO[si]);
            stcs(&out_r[oi], sRO[si]);
        }
        // z partial (output path; feedback source only when zf)
        if (tid < 128) {
            int bb2 = tid >> 3, oo = tid & 7;
            float s = 0.f;
#pragma unroll
            for (int j2 = 0; j2 < RPC; j2++) s = fmaf(sHT[j2 * 16 + bb2], sWo[oo * 16 + j2], s);
            stcs(&g_zt[(size_t)t * (NCTA * 128) + cta * 128 + tid], s);
        }
        if (zf) {
            __syncthreads();
            if (tid == 0) red_release(&g_zcnt[0]);
        }

        // ---- hoisted head of step t+1: wait own group, snapshot, prefetch c0 ----
        if (t + 1 < Tdim) {
            tgt += 32u;
            if (l == 0) {
                while (ldrelax(pc0) < tgt) {}
                while (ldacq(pc0) < tgt) {}
                f1 = (ldacq(pc1) >= tgt);
                f2 = (ldacq(pc2) >= tgt);
                f3 = (ldacq(pc3) >= tgt);
            }
            __syncwarp();
            prefetch(sV, g_v[nb], 0, c0, tid);
        }
    }
}

extern "C" void kernel_launch(void* const* d_in, const int* in_sizes, int n_in,
                              void* d_out, int out_size) {
    const float* x   = (const float*)d_in[0];
    const float* h0  = (const float*)d_in[1];
    const float* Wih = (const float*)d_in[2];
    const float* Wt  = (const float*)d_in[3];
    const float* Wf  = (const float*)d_in[4];
    const float* mk  = (const float*)d_in[5];
    const float* Whz = (const float*)d_in[6];
    const float* Wzh = (const float*)d_in[7];
    const float* tau = (const float*)d_in[8];
    float* out = (float*)d_out;

    reset_counters<<<1, 256>>>();
    scan_wzh<<<(Hdim * NOUT + 255) / 256, 256>>>(Wzh);
    build_wm<<<(Hdim * Hdim + 255) / 256, 256>>>(Wt, Wf, mk);

    cudaFuncSetAttribute(rnn_persist, cudaFuncAttributeMaxDynamicSharedMemorySize, 51392 * 4);
    rnn_persist<<<NCTA, NTH, 51392 * 4>>>(x, h0, Wih, Whz, Wzh, tau, out);

    zred<<<(Tdim * 128) / 256, 256>>>(out);
}